// round 12
// baseline (speedup 1.0000x reference)
#include <cuda_runtime.h>
#include <math.h>

#define NN 100000
#define NE 3200000
#define ELLW 96   // padded ELL row width; P(deg+1 > 96) ~ e^-60 for Poisson(32)

// ---------------- scratch (static device globals; no allocation) ----------------
__device__ int   d_deg[NN];
__device__ int   d_degR[NN];   // rounded row length (deg+self, padded to mult of 16)
__device__ __align__(16) int d_csr[(size_t)NN * ELLW];   // entries prescaled: src_node * 16
__device__ float d_dinv[NN];
// one extra zero row at index NN (dummy target for padded edges; never written)
__device__ __align__(16) float d_gbuf[2][(size_t)(NN + 1) * 16];

// ---------------- helpers ----------------
__device__ __forceinline__ float fast_tanh(float x) {
    float y;
    asm("tanh.approx.f32 %0, %1;" : "=f"(y) : "f"(x));
    return y;
}
__device__ __forceinline__ unsigned long long pack2(float x) {
    unsigned long long r;
    asm("mov.b64 %0, {%1, %1};" : "=l"(r) : "r"(__float_as_uint(x)));
    return r;
}
__device__ __forceinline__ void fma2(unsigned long long& acc,
                                     unsigned long long a, unsigned long long b) {
    asm("fma.rn.f32x2 %0, %1, %2, %0;" : "+l"(acc) : "l"(a), "l"(b));
}
__device__ __forceinline__ void add2(unsigned long long& a, unsigned long long b) {
    asm("add.rn.f32x2 %0, %0, %1;" : "+l"(a) : "l"(b));
}
__device__ __forceinline__ float2 unpack2(unsigned long long v) {
    float2 f;
    asm("mov.b64 {%0, %1}, %2;" : "=f"(f.x), "=f"(f.y) : "l"(v));
    return f;
}

// ---------------- graph build ----------------
__global__ void k_zero() {
    int i = blockIdx.x * blockDim.x + threadIdx.x;
    if (i < NN) d_deg[i] = 0;
}

// 8 edges per thread: 8 independent ATOMGs in flight (latency-bound kernel).
__global__ void k_fill(const int* __restrict__ src, const int* __restrict__ dst) {
    int i = blockIdx.x * blockDim.x + threadIdx.x;
    int e = i * 8;
    if (e >= NE) return;
    int4 sa = *(const int4*)(src + e);
    int4 sb = *(const int4*)(src + e + 4);
    int4 da = *(const int4*)(dst + e);
    int4 db = *(const int4*)(dst + e + 4);
    int s[8] = {sa.x, sa.y, sa.z, sa.w, sb.x, sb.y, sb.z, sb.w};
    int d[8] = {da.x, da.y, da.z, da.w, db.x, db.y, db.z, db.w};
    int p[8];
#pragma unroll
    for (int j = 0; j < 8; j++) p[j] = atomicAdd(&d_deg[d[j]], 1);
#pragma unroll
    for (int j = 0; j < 8; j++)
        if (p[j] < ELLW) d_csr[(size_t)d[j] * ELLW + p[j]] = s[j] * 16;
}

// ---- pad: append self-loop, pad row to mult of 16 with dummy, dinv, scale g0 ----
__global__ void k_pad() {
    int node = blockIdx.x * blockDim.x + threadIdx.x;
    if (node >= NN) return;
    int degr = d_deg[node];
    int deg  = min(degr, ELLW - 1);     // reserve one slot for the self-loop
    int* row = d_csr + (size_t)node * ELLW;
    row[deg] = node * 16;               // self-loop folded into the row
    int degR = (deg + 1 + 15) & ~15;
    for (int i = deg + 1; i < degR; i++) row[i] = NN * 16;   // zero-row dummies
    d_degR[node] = degR;
    float dv = rsqrtf((float)(degr + 1));
    d_dinv[node] = dv;
    float4* g = (float4*)(d_gbuf[0] + (size_t)node * 16);
#pragma unroll
    for (int j = 0; j < 4; j++) {
        float4 v = g[j];
        v.x *= dv; v.y *= dv; v.z *= dv; v.w *= dv;
        g[j] = v;
    }
}

// ---------------- MLP: x(131)->64->32->16, writes m = h3 @ Wc1 (pre-dinv) ----------------
// Does NOT read d_deg -> runs concurrently with k_fill.
__global__ void __launch_bounds__(128) k_mlp(
    const float* __restrict__ x,
    const float* __restrict__ W1, const float* __restrict__ b1,
    const float* __restrict__ W2, const float* __restrict__ b2,
    const float* __restrict__ W3, const float* __restrict__ b3,
    const float* __restrict__ Wc1)
{
    extern __shared__ float sm[];
    float* xs = sm;                    // 128*131
    float* w1 = xs + 128 * 131;        // 131*64
    float* w2 = w1 + 131 * 64;         // 64*32
    float* w3 = w2 + 64 * 32;          // 32*16
    float* wc = w3 + 32 * 16;          // 16*16
    float* bb = wc + 256;              // 64+32+16

    int t = threadIdx.x;
    int base = blockIdx.x * 128;

    for (int i = t; i < 131 * 64; i += 128) w1[i] = W1[i];
    for (int i = t; i < 64 * 32;  i += 128) w2[i] = W2[i];
    for (int i = t; i < 32 * 16;  i += 128) w3[i] = W3[i];
    for (int i = t; i < 256;      i += 128) wc[i] = Wc1[i];
    if (t < 64) bb[t]      = b1[t];
    if (t < 32) bb[64 + t] = b2[t];
    if (t < 16) bb[96 + t] = b3[t];

    int nvalid = min(128, NN - base);
    {
        int total = nvalid * 131;
        const float* xg = x + (size_t)base * 131;
        for (int i = t; i < total; i += 128) xs[i] = xg[i];
    }
    __syncthreads();
    if (t >= nvalid) return;
    int node = base + t;

    // layer 1: 131 -> 64 (packed f32x2)
    unsigned long long acc[32];
    const unsigned long long* bb2 = (const unsigned long long*)bb;
#pragma unroll
    for (int j = 0; j < 32; j++) acc[j] = bb2[j];
    const float* xr = xs + t * 131;
#pragma unroll 4
    for (int k = 0; k < 131; k++) {
        unsigned long long xp = pack2(xr[k]);
        const unsigned long long* wr = (const unsigned long long*)(w1 + k * 64);
#pragma unroll
        for (int j = 0; j < 32; j++) fma2(acc[j], xp, wr[j]);
    }
    float h1[64];
#pragma unroll
    for (int j = 0; j < 32; j++) {
        float2 v = unpack2(acc[j]);
        h1[2 * j]     = fast_tanh(v.x);
        h1[2 * j + 1] = fast_tanh(v.y);
    }

    // layer 2: 64 -> 32
    unsigned long long a2[16];
    const unsigned long long* bb2b = (const unsigned long long*)(bb + 64);
#pragma unroll
    for (int j = 0; j < 16; j++) a2[j] = bb2b[j];
#pragma unroll 4
    for (int k = 0; k < 64; k++) {
        unsigned long long vp = pack2(h1[k]);
        const unsigned long long* wr = (const unsigned long long*)(w2 + k * 32);
#pragma unroll
        for (int j = 0; j < 16; j++) fma2(a2[j], vp, wr[j]);
    }
    float h2[32];
#pragma unroll
    for (int j = 0; j < 16; j++) {
        float2 v = unpack2(a2[j]);
        h2[2 * j]     = fast_tanh(v.x);
        h2[2 * j + 1] = fast_tanh(v.y);
    }

    // layer 3: 32 -> 16 (no tanh)
    unsigned long long a3[8];
    const unsigned long long* bb2c = (const unsigned long long*)(bb + 96);
#pragma unroll
    for (int j = 0; j < 8; j++) a3[j] = bb2c[j];
#pragma unroll 4
    for (int k = 0; k < 32; k++) {
        unsigned long long vp = pack2(h2[k]);
        const unsigned long long* wr = (const unsigned long long*)(w3 + k * 16);
#pragma unroll
        for (int j = 0; j < 8; j++) fma2(a3[j], vp, wr[j]);
    }
    float h3[16];
#pragma unroll
    for (int j = 0; j < 8; j++) {
        float2 v = unpack2(a3[j]);
        h3[2 * j]     = v.x;
        h3[2 * j + 1] = v.y;
    }

    // m = h3 @ Wc1 (scaled by dinv later in k_pad)
    unsigned long long g0[8];
#pragma unroll
    for (int j = 0; j < 8; j++) g0[j] = 0ull;
#pragma unroll
    for (int k = 0; k < 16; k++) {
        unsigned long long vp = pack2(h3[k]);
        const unsigned long long* wr = (const unsigned long long*)(wc + k * 16);
#pragma unroll
        for (int j = 0; j < 8; j++) fma2(g0[j], vp, wr[j]);
    }
    float* go = d_gbuf[0] + (size_t)node * 16;
#pragma unroll
    for (int j = 0; j < 8; j++) {
        float2 v = unpack2(g0[j]);
        go[2 * j]     = v.x;
        go[2 * j + 1] = v.y;
    }
}

// ---------------- conv: 2 nodes/warp, packed-f32x2 gather, slot-parallel epilogue ----
// lane = n*16 + s*4 + c : n = node-in-warp, s = edge slot (4), c = float4 column (4).
__global__ void __launch_bounds__(256) k_conv(
    int pin,
    const float* __restrict__ bvec,
    const float* __restrict__ Wn,     // W of NEXT conv (null when last)
    const float* __restrict__ Wcls,
    const float* __restrict__ bcls,
    float* __restrict__ outp,
    float* __restrict__ houtp,
    int last)
{
    __shared__ float ws[256];
    __shared__ float bs[16];
    __shared__ float wc[32];
    __shared__ float bc[2];

    int t = threadIdx.x;
    if (!last) {
        ws[t] = Wn[t];
    } else {
        if (t < 32) wc[t] = Wcls[t];
        if (t < 2)  bc[t] = bcls[t];
    }
    if (t < 16) bs[t] = bvec[t];
    __syncthreads();

    int wid  = t >> 5;
    int lane = t & 31;
    int s    = (lane >> 2) & 3;
    int c    = lane & 3;
    int node = blockIdx.x * 16 + wid * 2 + ((lane >> 4) & 1);
    if (node >= NN) return;

    const float* __restrict__ gin = d_gbuf[pin];
    float* __restrict__ gout = d_gbuf[pin ^ 1];

    int degR = d_degR[node];
    const int* __restrict__ row = d_csr + (size_t)node * ELLW + 4 * s;
    const float* __restrict__ ginc = gin + c * 4;

    // 4 independent packed accumulator chains
    unsigned long long A0 = 0ull, A1 = 0ull, B0 = 0ull, B1 = 0ull;

    for (int cb = 0; cb < degR; cb += 16) {
        int4 id = *(const int4*)(row + cb);
        ulonglong2 v0 = *(const ulonglong2*)(ginc + id.x);
        ulonglong2 v1 = *(const ulonglong2*)(ginc + id.y);
        ulonglong2 v2 = *(const ulonglong2*)(ginc + id.z);
        ulonglong2 v3 = *(const ulonglong2*)(ginc + id.w);
        add2(A0, v0.x); add2(A1, v0.y);
        add2(B0, v1.x); add2(B1, v1.y);
        add2(A0, v2.x); add2(A1, v2.y);
        add2(B0, v3.x); add2(B1, v3.y);
    }
    add2(A0, B0); add2(A1, B1);
    float2 lo = unpack2(A0), hi = unpack2(A1);
    float4 acc = make_float4(lo.x, lo.y, hi.x, hi.y);

    // reduce across 4 slots (lane bits 2..3); all 16 lanes of the node get full sums
#pragma unroll
    for (int off = 8; off >= 4; off >>= 1) {
        acc.x += __shfl_xor_sync(0xffffffffu, acc.x, off);
        acc.y += __shfl_xor_sync(0xffffffffu, acc.y, off);
        acc.z += __shfl_xor_sync(0xffffffffu, acc.z, off);
        acc.w += __shfl_xor_sync(0xffffffffu, acc.w, off);
    }

    float dv = d_dinv[node];
    float4 h;
    h.x = fast_tanh(dv * acc.x + bs[c * 4 + 0]);
    h.y = fast_tanh(dv * acc.y + bs[c * 4 + 1]);
    h.z = fast_tanh(dv * acc.z + bs[c * 4 + 2]);
    h.w = fast_tanh(dv * acc.w + bs[c * 4 + 3]);

    if (!last) {
        // slot-parallel epilogue: slot s handles k in {4s..4s+3} of the 16x16 matmul.
        // h features 4s..4s+3 live on the lane with (same n, slot 0, c = s).
        int src = (lane & 16) | s;
        float4 hk;
        hk.x = __shfl_sync(0xffffffffu, h.x, src);
        hk.y = __shfl_sync(0xffffffffu, h.y, src);
        hk.z = __shfl_sync(0xffffffffu, h.z, src);
        hk.w = __shfl_sync(0xffffffffu, h.w, src);

        const float4 w0 = *(const float4*)(ws + (4 * s + 0) * 16 + c * 4);
        const float4 w1 = *(const float4*)(ws + (4 * s + 1) * 16 + c * 4);
        const float4 w2 = *(const float4*)(ws + (4 * s + 2) * 16 + c * 4);
        const float4 w3 = *(const float4*)(ws + (4 * s + 3) * 16 + c * 4);
        float4 gn;
        gn.x = hk.x * w0.x + hk.y * w1.x + hk.z * w2.x + hk.w * w3.x;
        gn.y = hk.x * w0.y + hk.y * w1.y + hk.z * w2.y + hk.w * w3.y;
        gn.z = hk.x * w0.z + hk.y * w1.z + hk.z * w2.z + hk.w * w3.z;
        gn.w = hk.x * w0.w + hk.y * w1.w + hk.z * w2.w + hk.w * w3.w;
#pragma unroll
        for (int off = 8; off >= 4; off >>= 1) {
            gn.x += __shfl_xor_sync(0xffffffffu, gn.x, off);
            gn.y += __shfl_xor_sync(0xffffffffu, gn.y, off);
            gn.z += __shfl_xor_sync(0xffffffffu, gn.z, off);
            gn.w += __shfl_xor_sync(0xffffffffu, gn.w, off);
        }
        if (s == 0) {
            gn.x *= dv; gn.y *= dv; gn.z *= dv; gn.w *= dv;
            *(float4*)(gout + (size_t)node * 16 + c * 4) = gn;
        }
    } else {
        if (s == 0)
            *(float4*)(houtp + (size_t)node * 16 + c * 4) = h;
        // out = h @ Wcls + bcls : reduce partials across the 4 c-lanes
        float o0 = h.x * wc[(c * 4 + 0) * 2 + 0] + h.y * wc[(c * 4 + 1) * 2 + 0]
                 + h.z * wc[(c * 4 + 2) * 2 + 0] + h.w * wc[(c * 4 + 3) * 2 + 0];
        float o1 = h.x * wc[(c * 4 + 0) * 2 + 1] + h.y * wc[(c * 4 + 1) * 2 + 1]
                 + h.z * wc[(c * 4 + 2) * 2 + 1] + h.w * wc[(c * 4 + 3) * 2 + 1];
        o0 += __shfl_xor_sync(0xffffffffu, o0, 1);
        o0 += __shfl_xor_sync(0xffffffffu, o0, 2);
        o1 += __shfl_xor_sync(0xffffffffu, o1, 1);
        o1 += __shfl_xor_sync(0xffffffffu, o1, 2);
        if ((lane & 15) == 0) {
            outp[(size_t)node * 2 + 0] = o0 + bc[0];
            outp[(size_t)node * 2 + 1] = o1 + bc[1];
        }
    }
}

// ---------------- launch ----------------
extern "C" void kernel_launch(void* const* d_in, const int* in_sizes, int n_in,
                              void* d_out, int out_size)
{
    const float* x    = (const float*)d_in[0];
    const int*   ei   = (const int*)  d_in[1];
    const float* W1   = (const float*)d_in[2];
    const float* b1   = (const float*)d_in[3];
    const float* W2   = (const float*)d_in[4];
    const float* b2   = (const float*)d_in[5];
    const float* W3   = (const float*)d_in[6];
    const float* b3   = (const float*)d_in[7];
    const float* Wc1  = (const float*)d_in[8];
    const float* bc1  = (const float*)d_in[9];
    const float* Wg   = (const float*)d_in[10];
    const float* bg   = (const float*)d_in[11];
    const float* Wcls = (const float*)d_in[12];
    const float* bcls = (const float*)d_in[13];

    const int* srcp = ei;
    const int* dstp = ei + NE;
    float* outp  = (float*)d_out;
    float* houtp = outp + (size_t)NN * 2;

    // once-only side stream + fork/join events (capture-legal pattern)
    static cudaStream_t s2 = nullptr;
    static cudaEvent_t e1 = nullptr, e2 = nullptr;
    if (!s2) {
        cudaStreamCreateWithFlags(&s2, cudaStreamNonBlocking);
        cudaEventCreateWithFlags(&e1, cudaEventDisableTiming);
        cudaEventCreateWithFlags(&e2, cudaEventDisableTiming);
    }

    // main: zero degrees; side: fill (ATOMG-latency bound) overlapped with MLP (FFMA bound)
    k_zero<<<(NN + 255) / 256, 256>>>();
    cudaEventRecord(e1, 0);
    cudaStreamWaitEvent(s2, e1, 0);
    k_fill<<<(NE / 8 + 255) / 256, 256, 0, s2>>>(srcp, dstp);
    cudaEventRecord(e2, s2);

    int smem = (128 * 131 + 131 * 64 + 64 * 32 + 32 * 16 + 256 + 112) * 4;
    cudaFuncSetAttribute(k_mlp, cudaFuncAttributeMaxDynamicSharedMemorySize, smem);
    k_mlp<<<(NN + 127) / 128, 128, smem>>>(x, W1, b1, W2, b2, W3, b3, Wc1);

    // join, then pad + self-loop + dinv + g0 scale
    cudaStreamWaitEvent(0, e2, 0);
    k_pad<<<(NN + 255) / 256, 256>>>();

    for (int k = 0; k < 10; k++) {
        const float* bv = (k < 5) ? bc1 : bg + (size_t)(k - 5) * 16;
        int last = (k == 9);
        const float* Wn = nullptr;
        if (!last) Wn = (k + 1 < 5) ? Wc1 : Wg + (size_t)(k + 1 - 5) * 256;
        k_conv<<<(NN + 15) / 16, 256>>>(k & 1, bv, Wn, Wcls, bcls, outp, houtp, last);
    }
}

// round 13
// speedup vs baseline: 1.0051x; 1.0051x over previous
#include <cuda_runtime.h>
#include <math.h>

#define NN 100000
#define NE 3200000
#define ELLW 96   // padded ELL row width; P(deg+1 > 96) ~ e^-60 for Poisson(32)

// ---------------- scratch (static device globals; no allocation) ----------------
__device__ int   d_deg[NN];
__device__ int   d_degR[NN];   // rounded row length (deg+self, padded to mult of 16)
// +16 tail pad so the index-prefetch beyond the last row stays in-bounds
__device__ __align__(16) int d_csr[(size_t)NN * ELLW + 16];  // entries prescaled: src*16
__device__ float d_dinv[NN];
// one extra zero row at index NN (dummy target for padded edges; never written)
__device__ __align__(16) float d_gbuf[2][(size_t)(NN + 1) * 16];

// ---------------- helpers ----------------
__device__ __forceinline__ float fast_tanh(float x) {
    float y;
    asm("tanh.approx.f32 %0, %1;" : "=f"(y) : "f"(x));
    return y;
}
__device__ __forceinline__ unsigned long long pack2(float x) {
    unsigned long long r;
    asm("mov.b64 %0, {%1, %1};" : "=l"(r) : "r"(__float_as_uint(x)));
    return r;
}
__device__ __forceinline__ void fma2(unsigned long long& acc,
                                     unsigned long long a, unsigned long long b) {
    asm("fma.rn.f32x2 %0, %1, %2, %0;" : "+l"(acc) : "l"(a), "l"(b));
}
__device__ __forceinline__ void add2(unsigned long long& a, unsigned long long b) {
    asm("add.rn.f32x2 %0, %0, %1;" : "+l"(a) : "l"(b));
}
__device__ __forceinline__ float2 unpack2(unsigned long long v) {
    float2 f;
    asm("mov.b64 {%0, %1}, %2;" : "=f"(f.x), "=f"(f.y) : "l"(v));
    return f;
}

// ---------------- graph build ----------------
__global__ void k_zero() {
    int i = blockIdx.x * blockDim.x + threadIdx.x;
    if (i < NN) d_deg[i] = 0;
}

// 8 edges per thread: 8 independent ATOMGs in flight (latency-bound kernel).
__global__ void k_fill(const int* __restrict__ src, const int* __restrict__ dst) {
    int i = blockIdx.x * blockDim.x + threadIdx.x;
    int e = i * 8;
    if (e >= NE) return;
    int4 sa = *(const int4*)(src + e);
    int4 sb = *(const int4*)(src + e + 4);
    int4 da = *(const int4*)(dst + e);
    int4 db = *(const int4*)(dst + e + 4);
    int s[8] = {sa.x, sa.y, sa.z, sa.w, sb.x, sb.y, sb.z, sb.w};
    int d[8] = {da.x, da.y, da.z, da.w, db.x, db.y, db.z, db.w};
    int p[8];
#pragma unroll
    for (int j = 0; j < 8; j++) p[j] = atomicAdd(&d_deg[d[j]], 1);
#pragma unroll
    for (int j = 0; j < 8; j++)
        if (p[j] < ELLW) d_csr[(size_t)d[j] * ELLW + p[j]] = s[j] * 16;
}

// ---- pad (4 lanes per node): self-loop, pad row to mult of 16, dinv, scale g0 ----
__global__ void k_pad() {
    int tid  = blockIdx.x * blockDim.x + threadIdx.x;
    int node = tid >> 2;
    int j    = tid & 3;
    if (node >= NN) return;
    int degr = d_deg[node];
    int deg  = min(degr, ELLW - 1);     // reserve one slot for the self-loop
    int degR = (deg + 1 + 15) & ~15;
    int* row = d_csr + (size_t)node * ELLW;
    if (j == 0) {
        row[deg] = node * 16;           // self-loop folded into the row
        d_degR[node] = degR;
        d_dinv[node] = rsqrtf((float)(degr + 1));
    }
    for (int i = deg + 1 + j; i < degR; i += 4)
        row[i] = NN * 16;               // zero-row dummies
    float dv = rsqrtf((float)(degr + 1));
    float4* g = (float4*)(d_gbuf[0] + (size_t)node * 16);
    float4 v = g[j];
    v.x *= dv; v.y *= dv; v.z *= dv; v.w *= dv;
    g[j] = v;
}

// ---------------- MLP: x(131)->64->32->16, writes m = h3 @ Wc1 (pre-dinv) ----------------
// Does NOT read d_deg -> runs concurrently with k_fill.
__global__ void __launch_bounds__(128) k_mlp(
    const float* __restrict__ x,
    const float* __restrict__ W1, const float* __restrict__ b1,
    const float* __restrict__ W2, const float* __restrict__ b2,
    const float* __restrict__ W3, const float* __restrict__ b3,
    const float* __restrict__ Wc1)
{
    extern __shared__ float sm[];
    float* xs = sm;                    // 128*131
    float* w1 = xs + 128 * 131;        // 131*64
    float* w2 = w1 + 131 * 64;         // 64*32
    float* w3 = w2 + 64 * 32;          // 32*16
    float* wc = w3 + 32 * 16;          // 16*16
    float* bb = wc + 256;              // 64+32+16

    int t = threadIdx.x;
    int base = blockIdx.x * 128;

    for (int i = t; i < 131 * 64; i += 128) w1[i] = W1[i];
    for (int i = t; i < 64 * 32;  i += 128) w2[i] = W2[i];
    for (int i = t; i < 32 * 16;  i += 128) w3[i] = W3[i];
    for (int i = t; i < 256;      i += 128) wc[i] = Wc1[i];
    if (t < 64) bb[t]      = b1[t];
    if (t < 32) bb[64 + t] = b2[t];
    if (t < 16) bb[96 + t] = b3[t];

    int nvalid = min(128, NN - base);
    {
        int total = nvalid * 131;
        const float* xg = x + (size_t)base * 131;
        for (int i = t; i < total; i += 128) xs[i] = xg[i];
    }
    __syncthreads();
    if (t >= nvalid) return;
    int node = base + t;

    // layer 1: 131 -> 64 (packed f32x2)
    unsigned long long acc[32];
    const unsigned long long* bb2 = (const unsigned long long*)bb;
#pragma unroll
    for (int j = 0; j < 32; j++) acc[j] = bb2[j];
    const float* xr = xs + t * 131;
#pragma unroll 4
    for (int k = 0; k < 131; k++) {
        unsigned long long xp = pack2(xr[k]);
        const unsigned long long* wr = (const unsigned long long*)(w1 + k * 64);
#pragma unroll
        for (int j = 0; j < 32; j++) fma2(acc[j], xp, wr[j]);
    }
    float h1[64];
#pragma unroll
    for (int j = 0; j < 32; j++) {
        float2 v = unpack2(acc[j]);
        h1[2 * j]     = fast_tanh(v.x);
        h1[2 * j + 1] = fast_tanh(v.y);
    }

    // layer 2: 64 -> 32
    unsigned long long a2[16];
    const unsigned long long* bb2b = (const unsigned long long*)(bb + 64);
#pragma unroll
    for (int j = 0; j < 16; j++) a2[j] = bb2b[j];
#pragma unroll 4
    for (int k = 0; k < 64; k++) {
        unsigned long long vp = pack2(h1[k]);
        const unsigned long long* wr = (const unsigned long long*)(w2 + k * 32);
#pragma unroll
        for (int j = 0; j < 16; j++) fma2(a2[j], vp, wr[j]);
    }
    float h2[32];
#pragma unroll
    for (int j = 0; j < 16; j++) {
        float2 v = unpack2(a2[j]);
        h2[2 * j]     = fast_tanh(v.x);
        h2[2 * j + 1] = fast_tanh(v.y);
    }

    // layer 3: 32 -> 16 (no tanh)
    unsigned long long a3[8];
    const unsigned long long* bb2c = (const unsigned long long*)(bb + 96);
#pragma unroll
    for (int j = 0; j < 8; j++) a3[j] = bb2c[j];
#pragma unroll 4
    for (int k = 0; k < 32; k++) {
        unsigned long long vp = pack2(h2[k]);
        const unsigned long long* wr = (const unsigned long long*)(w3 + k * 16);
#pragma unroll
        for (int j = 0; j < 8; j++) fma2(a3[j], vp, wr[j]);
    }
    float h3[16];
#pragma unroll
    for (int j = 0; j < 8; j++) {
        float2 v = unpack2(a3[j]);
        h3[2 * j]     = v.x;
        h3[2 * j + 1] = v.y;
    }

    // m = h3 @ Wc1 (scaled by dinv later in k_pad)
    unsigned long long g0[8];
#pragma unroll
    for (int j = 0; j < 8; j++) g0[j] = 0ull;
#pragma unroll
    for (int k = 0; k < 16; k++) {
        unsigned long long vp = pack2(h3[k]);
        const unsigned long long* wr = (const unsigned long long*)(wc + k * 16);
#pragma unroll
        for (int j = 0; j < 8; j++) fma2(g0[j], vp, wr[j]);
    }
    float* go = d_gbuf[0] + (size_t)node * 16;
#pragma unroll
    for (int j = 0; j < 8; j++) {
        float2 v = unpack2(g0[j]);
        go[2 * j]     = v.x;
        go[2 * j + 1] = v.y;
    }
}

// ---------------- conv: 2 nodes/warp, prefetched packed gather, slot-parallel epilogue ----
// lane = n*16 + s*4 + c : n = node-in-warp, s = edge slot (4), c = float4 column (4).
__global__ void __launch_bounds__(256, 6) k_conv(
    int pin,
    const float* __restrict__ bvec,
    const float* __restrict__ Wn,     // W of NEXT conv (null when last)
    const float* __restrict__ Wcls,
    const float* __restrict__ bcls,
    float* __restrict__ outp,
    float* __restrict__ houtp,
    int last)
{
    __shared__ float ws[256];
    __shared__ float bs[16];
    __shared__ float wc[32];
    __shared__ float bc[2];

    int t = threadIdx.x;
    if (!last) {
        ws[t] = Wn[t];
    } else {
        if (t < 32) wc[t] = Wcls[t];
        if (t < 2)  bc[t] = bcls[t];
    }
    if (t < 16) bs[t] = bvec[t];
    __syncthreads();

    int wid  = t >> 5;
    int lane = t & 31;
    int s    = (lane >> 2) & 3;
    int c    = lane & 3;
    int node = blockIdx.x * 16 + wid * 2 + ((lane >> 4) & 1);
    if (node >= NN) return;

    const float* __restrict__ gin = d_gbuf[pin];
    float* __restrict__ gout = d_gbuf[pin ^ 1];

    int degR = d_degR[node];
    const int* __restrict__ row = d_csr + (size_t)node * ELLW + 4 * s;
    const float* __restrict__ ginc = gin + c * 4;

    // 4 independent packed accumulator chains; index quad prefetched one chunk ahead
    unsigned long long A0 = 0ull, A1 = 0ull, B0 = 0ull, B1 = 0ull;

    int4 id = *(const int4*)(row);
    for (int cb = 16; cb <= degR; cb += 16) {
        int4 idn = *(const int4*)(row + cb);   // tail-safe: d_csr has +16 pad
        ulonglong2 v0 = *(const ulonglong2*)(ginc + id.x);
        ulonglong2 v1 = *(const ulonglong2*)(ginc + id.y);
        ulonglong2 v2 = *(const ulonglong2*)(ginc + id.z);
        ulonglong2 v3 = *(const ulonglong2*)(ginc + id.w);
        add2(A0, v0.x); add2(A1, v0.y);
        add2(B0, v1.x); add2(B1, v1.y);
        add2(A0, v2.x); add2(A1, v2.y);
        add2(B0, v3.x); add2(B1, v3.y);
        id = idn;
    }
    add2(A0, B0); add2(A1, B1);
    float2 lo = unpack2(A0), hi = unpack2(A1);
    float4 acc = make_float4(lo.x, lo.y, hi.x, hi.y);

    // reduce across 4 slots (lane bits 2..3); all 16 lanes of the node get full sums
#pragma unroll
    for (int off = 8; off >= 4; off >>= 1) {
        acc.x += __shfl_xor_sync(0xffffffffu, acc.x, off);
        acc.y += __shfl_xor_sync(0xffffffffu, acc.y, off);
        acc.z += __shfl_xor_sync(0xffffffffu, acc.z, off);
        acc.w += __shfl_xor_sync(0xffffffffu, acc.w, off);
    }

    float dv = d_dinv[node];
    float4 h;
    h.x = fast_tanh(dv * acc.x + bs[c * 4 + 0]);
    h.y = fast_tanh(dv * acc.y + bs[c * 4 + 1]);
    h.z = fast_tanh(dv * acc.z + bs[c * 4 + 2]);
    h.w = fast_tanh(dv * acc.w + bs[c * 4 + 3]);

    if (!last) {
        // slot-parallel epilogue: slot s handles k in {4s..4s+3} of the 16x16 matmul.
        // h features 4s..4s+3 live on the lane with (same n, slot 0, c = s).
        int src = (lane & 16) | s;
        float4 hk;
        hk.x = __shfl_sync(0xffffffffu, h.x, src);
        hk.y = __shfl_sync(0xffffffffu, h.y, src);
        hk.z = __shfl_sync(0xffffffffu, h.z, src);
        hk.w = __shfl_sync(0xffffffffu, h.w, src);

        const float4 w0 = *(const float4*)(ws + (4 * s + 0) * 16 + c * 4);
        const float4 w1 = *(const float4*)(ws + (4 * s + 1) * 16 + c * 4);
        const float4 w2 = *(const float4*)(ws + (4 * s + 2) * 16 + c * 4);
        const float4 w3 = *(const float4*)(ws + (4 * s + 3) * 16 + c * 4);
        float4 gn;
        gn.x = hk.x * w0.x + hk.y * w1.x + hk.z * w2.x + hk.w * w3.x;
        gn.y = hk.x * w0.y + hk.y * w1.y + hk.z * w2.y + hk.w * w3.y;
        gn.z = hk.x * w0.z + hk.y * w1.z + hk.z * w2.z + hk.w * w3.z;
        gn.w = hk.x * w0.w + hk.y * w1.w + hk.z * w2.w + hk.w * w3.w;
#pragma unroll
        for (int off = 8; off >= 4; off >>= 1) {
            gn.x += __shfl_xor_sync(0xffffffffu, gn.x, off);
            gn.y += __shfl_xor_sync(0xffffffffu, gn.y, off);
            gn.z += __shfl_xor_sync(0xffffffffu, gn.z, off);
            gn.w += __shfl_xor_sync(0xffffffffu, gn.w, off);
        }
        if (s == 0) {
            gn.x *= dv; gn.y *= dv; gn.z *= dv; gn.w *= dv;
            *(float4*)(gout + (size_t)node * 16 + c * 4) = gn;
        }
    } else {
        if (s == 0)
            *(float4*)(houtp + (size_t)node * 16 + c * 4) = h;
        // out = h @ Wcls + bcls : reduce partials across the 4 c-lanes
        float o0 = h.x * wc[(c * 4 + 0) * 2 + 0] + h.y * wc[(c * 4 + 1) * 2 + 0]
                 + h.z * wc[(c * 4 + 2) * 2 + 0] + h.w * wc[(c * 4 + 3) * 2 + 0];
        float o1 = h.x * wc[(c * 4 + 0) * 2 + 1] + h.y * wc[(c * 4 + 1) * 2 + 1]
                 + h.z * wc[(c * 4 + 2) * 2 + 1] + h.w * wc[(c * 4 + 3) * 2 + 1];
        o0 += __shfl_xor_sync(0xffffffffu, o0, 1);
        o0 += __shfl_xor_sync(0xffffffffu, o0, 2);
        o1 += __shfl_xor_sync(0xffffffffu, o1, 1);
        o1 += __shfl_xor_sync(0xffffffffu, o1, 2);
        if ((lane & 15) == 0) {
            outp[(size_t)node * 2 + 0] = o0 + bc[0];
            outp[(size_t)node * 2 + 1] = o1 + bc[1];
        }
    }
}

// ---------------- launch ----------------
extern "C" void kernel_launch(void* const* d_in, const int* in_sizes, int n_in,
                              void* d_out, int out_size)
{
    const float* x    = (const float*)d_in[0];
    const int*   ei   = (const int*)  d_in[1];
    const float* W1   = (const float*)d_in[2];
    const float* b1   = (const float*)d_in[3];
    const float* W2   = (const float*)d_in[4];
    const float* b2   = (const float*)d_in[5];
    const float* W3   = (const float*)d_in[6];
    const float* b3   = (const float*)d_in[7];
    const float* Wc1  = (const float*)d_in[8];
    const float* bc1  = (const float*)d_in[9];
    const float* Wg   = (const float*)d_in[10];
    const float* bg   = (const float*)d_in[11];
    const float* Wcls = (const float*)d_in[12];
    const float* bcls = (const float*)d_in[13];

    const int* srcp = ei;
    const int* dstp = ei + NE;
    float* outp  = (float*)d_out;
    float* houtp = outp + (size_t)NN * 2;

    // once-only side stream + fork/join events (capture-legal pattern)
    static cudaStream_t s2 = nullptr;
    static cudaEvent_t e1 = nullptr, e2 = nullptr;
    if (!s2) {
        cudaStreamCreateWithFlags(&s2, cudaStreamNonBlocking);
        cudaEventCreateWithFlags(&e1, cudaEventDisableTiming);
        cudaEventCreateWithFlags(&e2, cudaEventDisableTiming);
    }

    // main: zero degrees; side: fill (ATOMG-latency bound) overlapped with MLP (FFMA bound)
    k_zero<<<(NN + 255) / 256, 256>>>();
    cudaEventRecord(e1, 0);
    cudaStreamWaitEvent(s2, e1, 0);
    k_fill<<<(NE / 8 + 255) / 256, 256, 0, s2>>>(srcp, dstp);
    cudaEventRecord(e2, s2);

    int smem = (128 * 131 + 131 * 64 + 64 * 32 + 32 * 16 + 256 + 112) * 4;
    cudaFuncSetAttribute(k_mlp, cudaFuncAttributeMaxDynamicSharedMemorySize, smem);
    k_mlp<<<(NN + 127) / 128, 128, smem>>>(x, W1, b1, W2, b2, W3, b3, Wc1);

    // join, then pad + self-loop + dinv + g0 scale (4 lanes per node)
    cudaStreamWaitEvent(0, e2, 0);
    k_pad<<<(NN * 4 + 255) / 256, 256>>>();

    for (int k = 0; k < 10; k++) {
        const float* bv = (k < 5) ? bc1 : bg + (size_t)(k - 5) * 16;
        int last = (k == 9);
        const float* Wn = nullptr;
        if (!last) Wn = (k + 1 < 5) ? Wc1 : Wg + (size_t)(k + 1 - 5) * 256;
        k_conv<<<(NN + 15) / 16, 256>>>(k & 1, bv, Wn, Wcls, bcls, outp, houtp, last);
    }
}